// round 8
// baseline (speedup 1.0000x reference)
#include <cuda_runtime.h>
#include <cuda_bf16.h>
#include <math.h>
#include <stdint.h>

#define D_MODEL 1024
#define NHEAD   16
#define HEAD_DIM 64
#define BATCH   2
#define SEQ     2048
#define NTOK    (BATCH * SEQ)   // 4096

// ------------------------- scratch (no allocations allowed) -------------------------
__device__ __nv_bfloat16 g_xn [NTOK * D_MODEL];
__device__ __nv_bfloat16 g_q  [NTOK * D_MODEL];
__device__ __nv_bfloat16 g_k  [NTOK * D_MODEL];
__device__ __nv_bfloat16 g_v  [NTOK * D_MODEL];
__device__ __nv_bfloat16 g_att[NTOK * D_MODEL];
__device__ __nv_bfloat16 g_w  [4 * D_MODEL * D_MODEL];   // bf16 Wq,Wk,Wv,Wo
__device__ float2        g_rope[SEQ * 32];               // cos/sin table

// ------------------------------- helpers --------------------------------------------
__device__ __forceinline__ void mma_bf16(float* d, const uint32_t* a, const uint32_t* b) {
    asm volatile(
        "mma.sync.aligned.m16n8k16.row.col.f32.bf16.bf16.f32 "
        "{%0,%1,%2,%3}, {%4,%5,%6,%7}, {%8,%9}, {%0,%1,%2,%3};"
        : "+f"(d[0]), "+f"(d[1]), "+f"(d[2]), "+f"(d[3])
        : "r"(a[0]), "r"(a[1]), "r"(a[2]), "r"(a[3]), "r"(b[0]), "r"(b[1]));
}
__device__ __forceinline__ void ldm4(uint32_t* r, uint32_t a) {
    asm volatile("ldmatrix.sync.aligned.m8n8.x4.shared.b16 {%0,%1,%2,%3}, [%4];"
        : "=r"(r[0]), "=r"(r[1]), "=r"(r[2]), "=r"(r[3]) : "r"(a));
}
__device__ __forceinline__ void ldm4t(uint32_t* r, uint32_t a) {
    asm volatile("ldmatrix.sync.aligned.m8n8.x4.trans.shared.b16 {%0,%1,%2,%3}, [%4];"
        : "=r"(r[0]), "=r"(r[1]), "=r"(r[2]), "=r"(r[3]) : "r"(a));
}
__device__ __forceinline__ uint32_t smem_u32(const void* p) {
    return (uint32_t)__cvta_generic_to_shared(p);
}
__device__ __forceinline__ void cp16(uint32_t s, const void* g) {
    asm volatile("cp.async.cg.shared.global [%0], [%1], 16;" :: "r"(s), "l"(g));
}
#define CP_COMMIT   asm volatile("cp.async.commit_group;")
#define CP_WAIT_GROUP(n) asm volatile("cp.async.wait_group %0;" :: "n"(n))

// ------------------------------- rope table -----------------------------------------
__global__ __launch_bounds__(256) void rope_table_kernel(float2* __restrict__ tab) {
    const int idx = blockIdx.x * 256 + threadIdx.x;   // < SEQ*32
    const int pos = idx >> 5, j = idx & 31;
    const float inv = expf(-(float)(2 * j) * (9.210340371976184f / 64.f));
    float sn, cs;
    sincosf((float)pos * inv, &sn, &cs);
    tab[idx] = make_float2(cs, sn);
}

// ------------------------------- weight pre-round to bf16 ---------------------------
__global__ __launch_bounds__(256) void round_w_kernel(const float* __restrict__ a,
                                                      const float* __restrict__ b,
                                                      const float* __restrict__ c,
                                                      const float* __restrict__ d,
                                                      __nv_bfloat16* __restrict__ o) {
    const int i = blockIdx.x * 256 + threadIdx.x;          // float4 index
    const int n4 = D_MODEL * D_MODEL / 4;
    const float4 va = reinterpret_cast<const float4*>(a)[i];
    const float4 vb = reinterpret_cast<const float4*>(b)[i];
    const float4 vc = reinterpret_cast<const float4*>(c)[i];
    const float4 vd = reinterpret_cast<const float4*>(d)[i];
    uint2 u;
    __nv_bfloat162 h0, h1;
    h0 = __floats2bfloat162_rn(va.x, va.y); h1 = __floats2bfloat162_rn(va.z, va.w);
    u.x = *(uint32_t*)&h0; u.y = *(uint32_t*)&h1;
    *(uint2*)(o + (size_t)i * 4) = u;
    h0 = __floats2bfloat162_rn(vb.x, vb.y); h1 = __floats2bfloat162_rn(vb.z, vb.w);
    u.x = *(uint32_t*)&h0; u.y = *(uint32_t*)&h1;
    *(uint2*)(o + (size_t)(n4 + i) * 4) = u;
    h0 = __floats2bfloat162_rn(vc.x, vc.y); h1 = __floats2bfloat162_rn(vc.z, vc.w);
    u.x = *(uint32_t*)&h0; u.y = *(uint32_t*)&h1;
    *(uint2*)(o + (size_t)(2 * n4 + i) * 4) = u;
    h0 = __floats2bfloat162_rn(vd.x, vd.y); h1 = __floats2bfloat162_rn(vd.z, vd.w);
    u.x = *(uint32_t*)&h0; u.y = *(uint32_t*)&h1;
    *(uint2*)(o + (size_t)(3 * n4 + i) * 4) = u;
}

// ------------------------------- LayerNorm (bf16 out) -------------------------------
__global__ __launch_bounds__(256) void ln_kernel(const float* __restrict__ x,
                                                 const float* __restrict__ w,
                                                 const float* __restrict__ b,
                                                 __nv_bfloat16* __restrict__ y) {
    const int t   = blockIdx.x;
    const int tid = threadIdx.x;
    const float4* xr = reinterpret_cast<const float4*>(x + (size_t)t * D_MODEL);
    float4 v = xr[tid];

    __shared__ float red[8];
    float s = v.x + v.y + v.z + v.w;
    #pragma unroll
    for (int m = 16; m >= 1; m >>= 1) s += __shfl_xor_sync(0xffffffffu, s, m);
    if ((tid & 31) == 0) red[tid >> 5] = s;
    __syncthreads();
    float tot = 0.f;
    #pragma unroll
    for (int i = 0; i < 8; ++i) tot += red[i];
    const float mu = tot * (1.0f / D_MODEL);
    __syncthreads();

    const float dx = v.x - mu, dy = v.y - mu, dz = v.z - mu, dw = v.w - mu;
    float sq = dx*dx + dy*dy + dz*dz + dw*dw;
    #pragma unroll
    for (int m = 16; m >= 1; m >>= 1) sq += __shfl_xor_sync(0xffffffffu, sq, m);
    if ((tid & 31) == 0) red[tid >> 5] = sq;
    __syncthreads();
    float tot2 = 0.f;
    #pragma unroll
    for (int i = 0; i < 8; ++i) tot2 += red[i];
    const float rstd = rsqrtf(tot2 * (1.0f / D_MODEL) + 1e-5f);

    const float4 wv = reinterpret_cast<const float4*>(w)[tid];
    const float4 bv = reinterpret_cast<const float4*>(b)[tid];
    __nv_bfloat162 h0 = __floats2bfloat162_rn(dx * rstd * wv.x + bv.x, dy * rstd * wv.y + bv.y);
    __nv_bfloat162 h1 = __floats2bfloat162_rn(dz * rstd * wv.z + bv.z, dw * rstd * wv.w + bv.w);
    uint2 u; u.x = *(uint32_t*)&h0; u.y = *(uint32_t*)&h1;
    *(uint2*)(y + (size_t)t * D_MODEL + tid * 4) = u;
}

// ------------------------- bf16 tensor-core GEMM: C = A * W^T (+bias)(+resid) -------
// A: [M,K] bf16 row-major, W: [N,K] bf16 row-major.
// CTA tile 128x256x64, warp tile 64x64 (2x4 warps), 3-stage cp.async pipeline.
#define TBM 128
#define TBN 256
#define GSTG_A 18432                       // 128 rows * 144B
#define GSTG_B 36864                       // 256 rows * 144B
#define STAGE_B (GSTG_A + GSTG_B)          // 55296
#define GEMM_SMEM (3 * STAGE_B)            // 165888

// rope_mode: 0 = none, 1 = rope (k), 2 = rope + 0.125 scale (q)
struct GemmOut {
    void* C;
    const float* bias;
    const float* resid;
    const float2* rope;
    int bf16_out;
    int rope_mode;
};

__device__ __forceinline__ void gemm_body(const __nv_bfloat16* __restrict__ A,
                                          const __nv_bfloat16* __restrict__ W,
                                          const GemmOut& out,
                                          int m0, int n0, char* smem) {
    const uint32_t sb = smem_u32(smem);
    const int tid  = threadIdx.x;
    const int wid  = tid >> 5, lane = tid & 31;
    const int wm   = wid >> 2, wn   = wid & 3;     // 2 x 4 warps, warp tile 64x64
    const int g    = lane >> 2, t   = lane & 3;

    float acc[4][8][4];
    #pragma unroll
    for (int a = 0; a < 4; ++a)
        #pragma unroll
        for (int b = 0; b < 8; ++b)
            #pragma unroll
            for (int c = 0; c < 4; ++c) acc[a][b][c] = 0.f;

    const uint32_t a_row = (uint32_t)(lane & 15);
    const uint32_t a_cb  = (uint32_t)((lane >> 4) << 4);
    const uint32_t b_row = (uint32_t)((lane & 7) + ((lane >> 4) << 3));
    const uint32_t b_cb  = (uint32_t)(((lane >> 3) & 1) << 4);

    // fill: A 1024 chunks (4/thread) + B 2048 chunks (8/thread)
    #define GF(s_, kt_) do {                                                        \
        const int kk_ = (kt_) * 64;                                                 \
        _Pragma("unroll")                                                           \
        for (int c_ = 0; c_ < 4; ++c_) {                                            \
            const int j_ = tid + (c_ << 8);                                         \
            const int r_ = j_ >> 3, cc_ = j_ & 7;                                   \
            cp16(sb + (s_) * STAGE_B + r_ * 144 + cc_ * 16,                         \
                 A + (size_t)(m0 + r_) * D_MODEL + kk_ + cc_ * 8);                  \
        }                                                                           \
        _Pragma("unroll")                                                           \
        for (int c_ = 0; c_ < 8; ++c_) {                                            \
            const int j_ = tid + (c_ << 8);                                         \
            const int r_ = j_ >> 3, cc_ = j_ & 7;                                   \
            cp16(sb + (s_) * STAGE_B + GSTG_A + r_ * 144 + cc_ * 16,                \
                 W + (size_t)(n0 + r_) * D_MODEL + kk_ + cc_ * 8);                  \
        }                                                                           \
    } while (0)

    GF(0, 0);
    CP_COMMIT;
    GF(1, 1);
    CP_COMMIT;

    int s = 0, sf = 2;
    #pragma unroll 1
    for (int tt = 0; tt < D_MODEL / 64; ++tt) {
        CP_WAIT_GROUP(1);      // stage s ready (copy issued 2 iters ago)
        __syncthreads();       // all warps done with stage sf's previous contents
        if (tt + 2 < D_MODEL / 64) GF(sf, tt + 2);
        CP_COMMIT;             // exactly one group per iteration
        const uint32_t ab = sb + s * STAGE_B;
        const uint32_t wb = ab + GSTG_A;
        #pragma unroll
        for (int s16 = 0; s16 < 4; ++s16) {
            const uint32_t kb = s16 * 32;
            uint32_t af[4][4], b4[4][4];
            #pragma unroll
            for (int mf = 0; mf < 4; ++mf)
                ldm4(af[mf], ab + (wm * 64 + mf * 16 + a_row) * 144 + a_cb + kb);
            #pragma unroll
            for (int nfp = 0; nfp < 4; ++nfp)
                ldm4(b4[nfp], wb + (wn * 64 + nfp * 16 + b_row) * 144 + b_cb + kb);
            #pragma unroll
            for (int mf = 0; mf < 4; ++mf) {
                #pragma unroll
                for (int nfp = 0; nfp < 4; ++nfp) {
                    mma_bf16(acc[mf][nfp * 2],     af[mf], &b4[nfp][0]);
                    mma_bf16(acc[mf][nfp * 2 + 1], af[mf], &b4[nfp][2]);
                }
            }
        }
        if (++s == 3) s = 0;
        if (++sf == 3) sf = 0;
    }
    #undef GF

    #pragma unroll
    for (int mf = 0; mf < 4; ++mf) {
        #pragma unroll
        for (int nf = 0; nf < 8; ++nf) {
            const int n = n0 + wn * 64 + nf * 8 + 2 * t;
            const float2 bz = *(const float2*)(out.bias + n);
            #pragma unroll
            for (int h = 0; h < 2; ++h) {
                const int m = m0 + wm * 64 + mf * 16 + g + 8 * h;
                float2 r2;
                r2.x = acc[mf][nf][2 * h + 0] + bz.x;
                r2.y = acc[mf][nf][2 * h + 1] + bz.y;
                if (out.rope_mode) {
                    const int pos = m & (SEQ - 1);
                    const int j   = (n & 63) >> 1;
                    const float2 cs = out.rope[pos * 32 + j];
                    const float x0 = r2.x, x1 = r2.y;
                    r2.x = x0 * cs.x - x1 * cs.y;
                    r2.y = x0 * cs.y + x1 * cs.x;
                    if (out.rope_mode == 2) { r2.x *= 0.125f; r2.y *= 0.125f; }
                }
                if (out.resid) {
                    const float2 rv = *(const float2*)(out.resid + (size_t)m * D_MODEL + n);
                    r2.x += rv.x; r2.y += rv.y;
                }
                if (out.bf16_out) {
                    __nv_bfloat162 hh = __floats2bfloat162_rn(r2.x, r2.y);
                    *(__nv_bfloat162*)((__nv_bfloat16*)out.C + (size_t)m * D_MODEL + n) = hh;
                } else {
                    *(float2*)((float*)out.C + (size_t)m * D_MODEL + n) = r2;
                }
            }
        }
    }
}

// fused QKV: grid.x in [0,12): x>>2 -> {q,k,v}, (x&3)*256 -> n0
__global__ __launch_bounds__(256, 1) void gemm_qkv(const __nv_bfloat16* __restrict__ xn,
                                                   const __nv_bfloat16* __restrict__ wbuf,
                                                   const float* __restrict__ bq,
                                                   const float* __restrict__ bk,
                                                   const float* __restrict__ bv,
                                                   __nv_bfloat16* __restrict__ q,
                                                   __nv_bfloat16* __restrict__ k,
                                                   __nv_bfloat16* __restrict__ v,
                                                   const float2* __restrict__ rope) {
    extern __shared__ char smc[];
    const int which = blockIdx.x >> 2;
    const int n0    = (blockIdx.x & 3) * TBN;
    const int m0    = blockIdx.y * TBM;
    GemmOut o;
    if (which == 0)      { o.C = q; o.bias = bq; o.rope_mode = 2; }
    else if (which == 1) { o.C = k; o.bias = bk; o.rope_mode = 1; }
    else                 { o.C = v; o.bias = bv; o.rope_mode = 0; }
    o.resid = nullptr; o.bf16_out = 1; o.rope = rope;
    gemm_body(xn, wbuf + (size_t)which * D_MODEL * D_MODEL, o, m0, n0, smc);
}

__global__ __launch_bounds__(256, 1) void gemm_oproj(const __nv_bfloat16* __restrict__ att,
                                                     const __nv_bfloat16* __restrict__ Wo,
                                                     const float* __restrict__ bo,
                                                     const float* __restrict__ x,
                                                     float* __restrict__ out) {
    extern __shared__ char smc[];
    GemmOut o; o.C = out; o.bias = bo; o.resid = x; o.bf16_out = 0;
    o.rope = nullptr; o.rope_mode = 0;
    gemm_body(att, Wo, o, blockIdx.y * TBM, blockIdx.x * TBN, smc);
}

// ------------------------ flash attention, bf16 tensor cores ------------------------
// q-tile 128, k-tile 64, hd 64. 8 warps x 16 q-rows. 3-stage K/V cp.async ring.
// q is pre-scaled by 1/sqrt(hd); rope already applied.
#define AQ  128
#define AKT 64
#define NT  (SEQ / AKT)  // 32
#define QS_B (128 * 144)
#define KV_B (64 * 144)
// layout: Q | K0 V0 | K1 V1 | K2 V2 | P
#define ATT_SMEM (QS_B + 6 * KV_B + 128 * 144)   // 92160

__global__ __launch_bounds__(256, 2) void attn_tc(const __nv_bfloat16* __restrict__ qg,
                                                  const __nv_bfloat16* __restrict__ kg,
                                                  const __nv_bfloat16* __restrict__ vg,
                                                  __nv_bfloat16* __restrict__ og) {
    extern __shared__ char smc[];
    const uint32_t sb   = smem_u32(smc);
    const uint32_t qoff = sb;
    const uint32_t poff = sb + QS_B + 6 * KV_B;
    __nv_bfloat16* Psp = (__nv_bfloat16*)(smc + QS_B + 6 * KV_B);

    const int tid  = threadIdx.x, wid = tid >> 5, lane = tid & 31;
    const int g    = lane >> 2, t = lane & 3;
    const int q0   = blockIdx.x * AQ;
    const size_t cbase = (size_t)blockIdx.z * SEQ * D_MODEL + (size_t)blockIdx.y * HEAD_DIM;
    const int wrow = wid * 16;

    const uint32_t a_row = (uint32_t)(lane & 15);
    const uint32_t a_cb  = (uint32_t)((lane >> 4) << 4);
    const uint32_t b_row = (uint32_t)((lane & 7) + ((lane >> 4) << 3));
    const uint32_t b_cb  = (uint32_t)(((lane >> 3) & 1) << 4);

    #define AKV(s_, tt_) do {                                                       \
        const uint32_t kb_ = sb + QS_B + (s_) * 2 * KV_B;                           \
        _Pragma("unroll")                                                           \
        for (int c_ = 0; c_ < 2; ++c_) {                                            \
            const int j_ = tid + (c_ << 8);                                         \
            const int r_ = j_ >> 3, cc_ = j_ & 7;                                   \
            const size_t go_ = cbase + (size_t)((tt_) * AKT + r_) * D_MODEL + cc_ * 8; \
            cp16(kb_ + r_ * 144 + cc_ * 16, kg + go_);                              \
            cp16(kb_ + KV_B + r_ * 144 + cc_ * 16, vg + go_);                       \
        }                                                                           \
    } while (0)

    // prologue: Q + stage0 (group0), stage1 (group1)
    #pragma unroll
    for (int c = 0; c < 4; ++c) {
        const int j = tid + (c << 8);
        const int r = j >> 3, cc = j & 7;
        cp16(qoff + r * 144 + cc * 16, qg + cbase + (size_t)(q0 + r) * D_MODEL + cc * 8);
    }
    AKV(0, 0);
    CP_COMMIT;
    AKV(1, 1);
    CP_COMMIT;

    float oacc[8][4];
    float mst[2] = { -1e30f, -1e30f }, lst[2] = { 0.f, 0.f };
    #pragma unroll
    for (int df = 0; df < 8; ++df)
        #pragma unroll
        for (int c = 0; c < 4; ++c) oacc[df][c] = 0.f;

    int s = 0, sf = 2;
    #pragma unroll 1
    for (int kt = 0; kt < NT; ++kt) {
        const uint32_t koff = sb + QS_B + s * 2 * KV_B;
        const uint32_t voff = koff + KV_B;

        CP_WAIT_GROUP(1);      // stage s ready (issued 2 iters ago)
        __syncthreads();       // all warps done with stage sf's old contents
        if (kt + 2 < NT) AKV(sf, kt + 2);
        CP_COMMIT;

        // ---- S = Q K^T (q pre-scaled) ----
        float sacc[8][4];
        #pragma unroll
        for (int nf = 0; nf < 8; ++nf)
            #pragma unroll
            for (int c = 0; c < 4; ++c) sacc[nf][c] = 0.f;

        #pragma unroll
        for (int s16 = 0; s16 < 4; ++s16) {
            const uint32_t kb = s16 * 32;
            uint32_t af[4];
            ldm4(af, qoff + (wrow + a_row) * 144 + a_cb + kb);
            #pragma unroll
            for (int nfp = 0; nfp < 4; ++nfp) {
                uint32_t t4[4];
                ldm4(t4, koff + (nfp * 16 + b_row) * 144 + b_cb + kb);
                mma_bf16(sacc[nfp * 2],     af, &t4[0]);
                mma_bf16(sacc[nfp * 2 + 1], af, &t4[2]);
            }
        }

        // ---- online softmax (rows g, g+8; reduce over 4 lanes of thread-row) ----
        #pragma unroll
        for (int h = 0; h < 2; ++h) {
            float rm = -1e30f;
            #pragma unroll
            for (int nf = 0; nf < 8; ++nf)
                rm = fmaxf(rm, fmaxf(sacc[nf][2 * h], sacc[nf][2 * h + 1]));
            rm = fmaxf(rm, __shfl_xor_sync(0xffffffffu, rm, 1));
            rm = fmaxf(rm, __shfl_xor_sync(0xffffffffu, rm, 2));
            const float mnew = fmaxf(mst[h], rm);
            const float corr = __expf(mst[h] - mnew);
            float ps = 0.f;
            const int prow = wrow + g + 8 * h;
            #pragma unroll
            for (int nf = 0; nf < 8; ++nf) {
                const float p0 = __expf(sacc[nf][2 * h]     - mnew);
                const float p1 = __expf(sacc[nf][2 * h + 1] - mnew);
                ps += p0 + p1;
                *(__nv_bfloat162*)&Psp[prow * 72 + nf * 8 + 2 * t] = __floats2bfloat162_rn(p0, p1);
            }
            ps += __shfl_xor_sync(0xffffffffu, ps, 1);
            ps += __shfl_xor_sync(0xffffffffu, ps, 2);
            lst[h] = lst[h] * corr + ps;
            mst[h] = mnew;
            #pragma unroll
            for (int df = 0; df < 8; ++df) {
                oacc[df][2 * h]     *= corr;
                oacc[df][2 * h + 1] *= corr;
            }
        }
        __syncwarp();   // P is warp-local (each warp owns its 16 rows)

        // ---- O += P V ----
        #pragma unroll
        for (int s16 = 0; s16 < 4; ++s16) {
            const uint32_t kb = s16 * 32;
            uint32_t af[4];
            ldm4(af, poff + (wrow + a_row) * 144 + a_cb + kb);
            #pragma unroll
            for (int nfp = 0; nfp < 4; ++nfp) {
                uint32_t t4[4];
                ldm4t(t4, voff + (s16 * 16 + a_row) * 144 + a_cb + nfp * 32);
                mma_bf16(oacc[nfp * 2],     af, &t4[0]);
                mma_bf16(oacc[nfp * 2 + 1], af, &t4[2]);
            }
        }

        if (++s == 3) s = 0;
        if (++sf == 3) sf = 0;
    }
    #undef AKV

    // ---- finalize: /l, bf16 out (feeds o-proj GEMM) ----
    #pragma unroll
    for (int h = 0; h < 2; ++h) {
        const float inv = 1.f / lst[h];
        const int row = q0 + wrow + g + 8 * h;
        #pragma unroll
        for (int df = 0; df < 8; ++df) {
            __nv_bfloat162 o2 = __floats2bfloat162_rn(oacc[df][2 * h] * inv,
                                                      oacc[df][2 * h + 1] * inv);
            *(__nv_bfloat162*)(og + cbase + (size_t)row * D_MODEL + df * 8 + 2 * t) = o2;
        }
    }
}

// ---------------------------------- launch ------------------------------------------
extern "C" void kernel_launch(void* const* d_in, const int* in_sizes, int n_in,
                              void* d_out, int out_size) {
    const float* x    = (const float*)d_in[0];
    const float* ln_w = (const float*)d_in[1];
    const float* ln_b = (const float*)d_in[2];
    const float* Wq   = (const float*)d_in[3];
    const float* bq   = (const float*)d_in[4];
    const float* Wk   = (const float*)d_in[5];
    const float* bk   = (const float*)d_in[6];
    const float* Wv   = (const float*)d_in[7];
    const float* bv   = (const float*)d_in[8];
    const float* Wo   = (const float*)d_in[9];
    const float* bo   = (const float*)d_in[10];
    float* out = (float*)d_out;

    __nv_bfloat16 *xn, *q, *k, *v, *att, *wbuf;
    float2* rope;
    cudaGetSymbolAddress((void**)&xn,  g_xn);
    cudaGetSymbolAddress((void**)&q,   g_q);
    cudaGetSymbolAddress((void**)&k,   g_k);
    cudaGetSymbolAddress((void**)&v,   g_v);
    cudaGetSymbolAddress((void**)&att, g_att);
    cudaGetSymbolAddress((void**)&wbuf, g_w);
    cudaGetSymbolAddress((void**)&rope, g_rope);
    const size_t WN = (size_t)D_MODEL * D_MODEL;

    rope_table_kernel<<<SEQ * 32 / 256, 256>>>(rope);
    round_w_kernel<<<(int)(WN / 4 / 256), 256>>>(Wq, Wk, Wv, Wo, wbuf);
    ln_kernel<<<NTOK, 256>>>(x, ln_w, ln_b, xn);

    cudaFuncSetAttribute(gemm_qkv,   cudaFuncAttributeMaxDynamicSharedMemorySize, GEMM_SMEM);
    cudaFuncSetAttribute(gemm_oproj, cudaFuncAttributeMaxDynamicSharedMemorySize, GEMM_SMEM);

    gemm_qkv<<<dim3(12, NTOK / TBM), 256, GEMM_SMEM>>>(xn, wbuf, bq, bk, bv, q, k, v, rope);

    cudaFuncSetAttribute(attn_tc, cudaFuncAttributeMaxDynamicSharedMemorySize, ATT_SMEM);
    attn_tc<<<dim3(SEQ / AQ, NHEAD, BATCH), 256, ATT_SMEM>>>(q, k, v, att);

    gemm_oproj<<<dim3(D_MODEL / TBN, NTOK / TBM), 256, GEMM_SMEM>>>(att, wbuf + 3 * WN, bo, x, out);
}

// round 9
// speedup vs baseline: 1.1180x; 1.1180x over previous
#include <cuda_runtime.h>
#include <cuda_bf16.h>
#include <math.h>
#include <stdint.h>

#define D_MODEL 1024
#define NHEAD   16
#define HEAD_DIM 64
#define BATCH   2
#define SEQ     2048
#define NTOK    (BATCH * SEQ)   // 4096

// ------------------------- scratch (no allocations allowed) -------------------------
__device__ __nv_bfloat16 g_xn [NTOK * D_MODEL];
__device__ __nv_bfloat16 g_q  [NTOK * D_MODEL];
__device__ __nv_bfloat16 g_k  [NTOK * D_MODEL];
__device__ __nv_bfloat16 g_v  [NTOK * D_MODEL];
__device__ __nv_bfloat16 g_att[NTOK * D_MODEL];
__device__ __nv_bfloat16 g_w  [4 * D_MODEL * D_MODEL];   // bf16 Wq,Wk,Wv,Wo
__device__ float2        g_rope[SEQ * 32];               // cos/sin table

// ------------------------------- helpers --------------------------------------------
__device__ __forceinline__ void mma_bf16(float* d, const uint32_t* a, const uint32_t* b) {
    asm volatile(
        "mma.sync.aligned.m16n8k16.row.col.f32.bf16.bf16.f32 "
        "{%0,%1,%2,%3}, {%4,%5,%6,%7}, {%8,%9}, {%0,%1,%2,%3};"
        : "+f"(d[0]), "+f"(d[1]), "+f"(d[2]), "+f"(d[3])
        : "r"(a[0]), "r"(a[1]), "r"(a[2]), "r"(a[3]), "r"(b[0]), "r"(b[1]));
}
__device__ __forceinline__ void ldm4(uint32_t* r, uint32_t a) {
    asm volatile("ldmatrix.sync.aligned.m8n8.x4.shared.b16 {%0,%1,%2,%3}, [%4];"
        : "=r"(r[0]), "=r"(r[1]), "=r"(r[2]), "=r"(r[3]) : "r"(a));
}
__device__ __forceinline__ void ldm4t(uint32_t* r, uint32_t a) {
    asm volatile("ldmatrix.sync.aligned.m8n8.x4.trans.shared.b16 {%0,%1,%2,%3}, [%4];"
        : "=r"(r[0]), "=r"(r[1]), "=r"(r[2]), "=r"(r[3]) : "r"(a));
}
__device__ __forceinline__ uint32_t smem_u32(const void* p) {
    return (uint32_t)__cvta_generic_to_shared(p);
}
__device__ __forceinline__ void cp16(uint32_t s, const void* g) {
    asm volatile("cp.async.cg.shared.global [%0], [%1], 16;" :: "r"(s), "l"(g));
}
__device__ __forceinline__ float ex2(float x) {
    float r;
    asm("ex2.approx.f32 %0, %1;" : "=f"(r) : "f"(x));
    return r;
}
#define CP_COMMIT   asm volatile("cp.async.commit_group;")
#define CP_WAIT_GROUP(n) asm volatile("cp.async.wait_group %0;" :: "n"(n))

// ------------------------------- rope table -----------------------------------------
__global__ __launch_bounds__(256) void rope_table_kernel(float2* __restrict__ tab) {
    const int idx = blockIdx.x * 256 + threadIdx.x;   // < SEQ*32
    const int pos = idx >> 5, j = idx & 31;
    const float inv = expf(-(float)(2 * j) * (9.210340371976184f / 64.f));
    float sn, cs;
    sincosf((float)pos * inv, &sn, &cs);
    tab[idx] = make_float2(cs, sn);
}

// ------------------------------- weight pre-round to bf16 ---------------------------
__global__ __launch_bounds__(256) void round_w_kernel(const float* __restrict__ a,
                                                      const float* __restrict__ b,
                                                      const float* __restrict__ c,
                                                      const float* __restrict__ d,
                                                      __nv_bfloat16* __restrict__ o) {
    const int i = blockIdx.x * 256 + threadIdx.x;          // float4 index
    const int n4 = D_MODEL * D_MODEL / 4;
    const float4 va = reinterpret_cast<const float4*>(a)[i];
    const float4 vb = reinterpret_cast<const float4*>(b)[i];
    const float4 vc = reinterpret_cast<const float4*>(c)[i];
    const float4 vd = reinterpret_cast<const float4*>(d)[i];
    uint2 u;
    __nv_bfloat162 h0, h1;
    h0 = __floats2bfloat162_rn(va.x, va.y); h1 = __floats2bfloat162_rn(va.z, va.w);
    u.x = *(uint32_t*)&h0; u.y = *(uint32_t*)&h1;
    *(uint2*)(o + (size_t)i * 4) = u;
    h0 = __floats2bfloat162_rn(vb.x, vb.y); h1 = __floats2bfloat162_rn(vb.z, vb.w);
    u.x = *(uint32_t*)&h0; u.y = *(uint32_t*)&h1;
    *(uint2*)(o + (size_t)(n4 + i) * 4) = u;
    h0 = __floats2bfloat162_rn(vc.x, vc.y); h1 = __floats2bfloat162_rn(vc.z, vc.w);
    u.x = *(uint32_t*)&h0; u.y = *(uint32_t*)&h1;
    *(uint2*)(o + (size_t)(2 * n4 + i) * 4) = u;
    h0 = __floats2bfloat162_rn(vd.x, vd.y); h1 = __floats2bfloat162_rn(vd.z, vd.w);
    u.x = *(uint32_t*)&h0; u.y = *(uint32_t*)&h1;
    *(uint2*)(o + (size_t)(3 * n4 + i) * 4) = u;
}

// ------------------------------- LayerNorm (bf16 out) -------------------------------
__global__ __launch_bounds__(256) void ln_kernel(const float* __restrict__ x,
                                                 const float* __restrict__ w,
                                                 const float* __restrict__ b,
                                                 __nv_bfloat16* __restrict__ y) {
    const int t   = blockIdx.x;
    const int tid = threadIdx.x;
    const float4* xr = reinterpret_cast<const float4*>(x + (size_t)t * D_MODEL);
    float4 v = xr[tid];

    __shared__ float red[8];
    float s = v.x + v.y + v.z + v.w;
    #pragma unroll
    for (int m = 16; m >= 1; m >>= 1) s += __shfl_xor_sync(0xffffffffu, s, m);
    if ((tid & 31) == 0) red[tid >> 5] = s;
    __syncthreads();
    float tot = 0.f;
    #pragma unroll
    for (int i = 0; i < 8; ++i) tot += red[i];
    const float mu = tot * (1.0f / D_MODEL);
    __syncthreads();

    const float dx = v.x - mu, dy = v.y - mu, dz = v.z - mu, dw = v.w - mu;
    float sq = dx*dx + dy*dy + dz*dz + dw*dw;
    #pragma unroll
    for (int m = 16; m >= 1; m >>= 1) sq += __shfl_xor_sync(0xffffffffu, sq, m);
    if ((tid & 31) == 0) red[tid >> 5] = sq;
    __syncthreads();
    float tot2 = 0.f;
    #pragma unroll
    for (int i = 0; i < 8; ++i) tot2 += red[i];
    const float rstd = rsqrtf(tot2 * (1.0f / D_MODEL) + 1e-5f);

    const float4 wv = reinterpret_cast<const float4*>(w)[tid];
    const float4 bv = reinterpret_cast<const float4*>(b)[tid];
    __nv_bfloat162 h0 = __floats2bfloat162_rn(dx * rstd * wv.x + bv.x, dy * rstd * wv.y + bv.y);
    __nv_bfloat162 h1 = __floats2bfloat162_rn(dz * rstd * wv.z + bv.z, dw * rstd * wv.w + bv.w);
    uint2 u; u.x = *(uint32_t*)&h0; u.y = *(uint32_t*)&h1;
    *(uint2*)(y + (size_t)t * D_MODEL + tid * 4) = u;
}

// ------------------------- bf16 tensor-core GEMM: C = A * W^T (+bias)(+resid) -------
// A: [M,K] bf16 row-major, W: [N,K] bf16 row-major. (R7 proven config.)
// CTA 128x128x64, warp tile 64x32 (2x4 warps), 3-stage cp.async pipeline.
#define TBM 128
#define TBN 128
#define GSTG 18432                         // bytes, one matrix one stage (128*144)
#define STAGE_B (2 * GSTG)                 // A + W per stage
#define GEMM_SMEM (3 * STAGE_B)            // 110592

// rope_mode: 0 = none, 1 = rope (k), 2 = rope + (log2e/8) scale (q)
struct GemmOut {
    void* C;
    const float* bias;
    const float* resid;
    const float2* rope;
    int bf16_out;
    int rope_mode;
};

__device__ __forceinline__ void gemm_body(const __nv_bfloat16* __restrict__ A,
                                          const __nv_bfloat16* __restrict__ W,
                                          const GemmOut& out,
                                          int m0, int n0, char* smem) {
    const uint32_t sb = smem_u32(smem);
    const int tid  = threadIdx.x;
    const int wid  = tid >> 5, lane = tid & 31;
    const int wm   = wid >> 2, wn   = wid & 3;     // 2 x 4 warps, warp tile 64x32
    const int g    = lane >> 2, t   = lane & 3;

    float acc[4][4][4];
    #pragma unroll
    for (int a = 0; a < 4; ++a)
        #pragma unroll
        for (int b = 0; b < 4; ++b)
            #pragma unroll
            for (int c = 0; c < 4; ++c) acc[a][b][c] = 0.f;

    const uint32_t a_row = (uint32_t)(lane & 15);
    const uint32_t a_cb  = (uint32_t)((lane >> 4) << 4);
    const uint32_t b_row = (uint32_t)((lane & 7) + ((lane >> 4) << 3));
    const uint32_t b_cb  = (uint32_t)(((lane >> 3) & 1) << 4);

    #define GF(s_, kt_) do {                                                        \
        const int kk_ = (kt_) * 64;                                                 \
        _Pragma("unroll")                                                           \
        for (int c_ = 0; c_ < 4; ++c_) {                                            \
            const int j_ = tid + (c_ << 8);                                         \
            const int r_ = j_ >> 3, cc_ = j_ & 7;                                   \
            cp16(sb + (s_) * STAGE_B + r_ * 144 + cc_ * 16,                         \
                 A + (size_t)(m0 + r_) * D_MODEL + kk_ + cc_ * 8);                  \
            cp16(sb + (s_) * STAGE_B + GSTG + r_ * 144 + cc_ * 16,                  \
                 W + (size_t)(n0 + r_) * D_MODEL + kk_ + cc_ * 8);                  \
        }                                                                           \
    } while (0)

    GF(0, 0);
    CP_COMMIT;
    GF(1, 1);
    CP_COMMIT;

    int s = 0, sf = 2;
    #pragma unroll 1
    for (int tt = 0; tt < D_MODEL / 64; ++tt) {
        CP_WAIT_GROUP(1);
        __syncthreads();
        if (tt + 2 < D_MODEL / 64) GF(sf, tt + 2);
        CP_COMMIT;
        const uint32_t ab = sb + s * STAGE_B;
        const uint32_t wb = ab + GSTG;
        #pragma unroll
        for (int s16 = 0; s16 < 4; ++s16) {
            const uint32_t kb = s16 * 32;
            uint32_t af[4][4], bf[4][4];
            #pragma unroll
            for (int mf = 0; mf < 4; ++mf)
                ldm4(af[mf], ab + (wm * 64 + mf * 16 + a_row) * 144 + a_cb + kb);
            #pragma unroll
            for (int nfp = 0; nfp < 2; ++nfp)
                ldm4(bf[nfp * 2], wb + (wn * 32 + nfp * 16 + b_row) * 144 + b_cb + kb);
            #pragma unroll
            for (int mf = 0; mf < 4; ++mf) {
                mma_bf16(acc[mf][0], af[mf], &bf[0][0]);
                mma_bf16(acc[mf][1], af[mf], &bf[0][2]);
                mma_bf16(acc[mf][2], af[mf], &bf[2][0]);
                mma_bf16(acc[mf][3], af[mf], &bf[2][2]);
            }
        }
        if (++s == 3) s = 0;
        if (++sf == 3) sf = 0;
    }
    #undef GF

    #pragma unroll
    for (int mf = 0; mf < 4; ++mf) {
        #pragma unroll
        for (int nf = 0; nf < 4; ++nf) {
            const int n = n0 + wn * 32 + nf * 8 + 2 * t;
            const float2 bz = *(const float2*)(out.bias + n);
            #pragma unroll
            for (int h = 0; h < 2; ++h) {
                const int m = m0 + wm * 64 + mf * 16 + g + 8 * h;
                float2 r2;
                r2.x = acc[mf][nf][2 * h + 0] + bz.x;
                r2.y = acc[mf][nf][2 * h + 1] + bz.y;
                if (out.rope_mode) {
                    const int pos = m & (SEQ - 1);
                    const int j   = (n & 63) >> 1;
                    const float2 cs = out.rope[pos * 32 + j];
                    const float x0 = r2.x, x1 = r2.y;
                    r2.x = x0 * cs.x - x1 * cs.y;
                    r2.y = x0 * cs.y + x1 * cs.x;
                    if (out.rope_mode == 2) {
                        // 1/sqrt(64) * log2(e): softmax uses ex2
                        r2.x *= 0.18033688011112042f;
                        r2.y *= 0.18033688011112042f;
                    }
                }
                if (out.resid) {
                    const float2 rv = *(const float2*)(out.resid + (size_t)m * D_MODEL + n);
                    r2.x += rv.x; r2.y += rv.y;
                }
                if (out.bf16_out) {
                    __nv_bfloat162 hh = __floats2bfloat162_rn(r2.x, r2.y);
                    *(__nv_bfloat162*)((__nv_bfloat16*)out.C + (size_t)m * D_MODEL + n) = hh;
                } else {
                    *(float2*)((float*)out.C + (size_t)m * D_MODEL + n) = r2;
                }
            }
        }
    }
}

// fused QKV: grid.x in [0,24): tiles 0-7 -> q (rope+scale), 8-15 -> k (rope), 16-23 -> v
__global__ __launch_bounds__(256, 2) void gemm_qkv(const __nv_bfloat16* __restrict__ xn,
                                                   const __nv_bfloat16* __restrict__ wbuf,
                                                   const float* __restrict__ bq,
                                                   const float* __restrict__ bk,
                                                   const float* __restrict__ bv,
                                                   __nv_bfloat16* __restrict__ q,
                                                   __nv_bfloat16* __restrict__ k,
                                                   __nv_bfloat16* __restrict__ v,
                                                   const float2* __restrict__ rope) {
    extern __shared__ char smc[];
    const int which = blockIdx.x >> 3;
    const int n0    = (blockIdx.x & 7) * TBN;
    const int m0    = blockIdx.y * TBM;
    GemmOut o;
    if (which == 0)      { o.C = q; o.bias = bq; o.rope_mode = 2; }
    else if (which == 1) { o.C = k; o.bias = bk; o.rope_mode = 1; }
    else                 { o.C = v; o.bias = bv; o.rope_mode = 0; }
    o.resid = nullptr; o.bf16_out = 1; o.rope = rope;
    gemm_body(xn, wbuf + (size_t)which * D_MODEL * D_MODEL, o, m0, n0, smc);
}

__global__ __launch_bounds__(256, 2) void gemm_oproj(const __nv_bfloat16* __restrict__ att,
                                                     const __nv_bfloat16* __restrict__ Wo,
                                                     const float* __restrict__ bo,
                                                     const float* __restrict__ x,
                                                     float* __restrict__ out) {
    extern __shared__ char smc[];
    GemmOut o; o.C = out; o.bias = bo; o.resid = x; o.bf16_out = 0;
    o.rope = nullptr; o.rope_mode = 0;
    gemm_body(att, Wo, o, blockIdx.y * TBM, blockIdx.x * TBN, smc);
}

// ------------------------ flash attention, bf16 tensor cores ------------------------
// q-tile 128, k-tile 64, hd 64. 8 warps x 16 q-rows. 3-stage K/V cp.async ring.
// q pre-scaled by log2e/sqrt(hd) -> softmax via ex2. P stays in registers (the S
// C-fragment layout IS the PV A-fragment layout after bf16x2 packing).
#define AQ  128
#define AKT 64
#define NT  (SEQ / AKT)  // 32
#define QS_B (128 * 144)
#define KV_B (64 * 144)
// layout: Q | K0 V0 | K1 V1 | K2 V2
#define ATT_SMEM (QS_B + 6 * KV_B)   // 73728

__global__ __launch_bounds__(256, 2) void attn_tc(const __nv_bfloat16* __restrict__ qg,
                                                  const __nv_bfloat16* __restrict__ kg,
                                                  const __nv_bfloat16* __restrict__ vg,
                                                  __nv_bfloat16* __restrict__ og) {
    extern __shared__ char smc[];
    const uint32_t sb   = smem_u32(smc);
    const uint32_t qoff = sb;

    const int tid  = threadIdx.x, wid = tid >> 5, lane = tid & 31;
    const int g    = lane >> 2, t = lane & 3;
    const int q0   = blockIdx.x * AQ;
    const size_t cbase = (size_t)blockIdx.z * SEQ * D_MODEL + (size_t)blockIdx.y * HEAD_DIM;
    const int wrow = wid * 16;

    const uint32_t a_row = (uint32_t)(lane & 15);
    const uint32_t a_cb  = (uint32_t)((lane >> 4) << 4);
    const uint32_t b_row = (uint32_t)((lane & 7) + ((lane >> 4) << 3));
    const uint32_t b_cb  = (uint32_t)(((lane >> 3) & 1) << 4);

    #define AKV(s_, tt_) do {                                                       \
        const uint32_t kb_ = sb + QS_B + (s_) * 2 * KV_B;                           \
        _Pragma("unroll")                                                           \
        for (int c_ = 0; c_ < 2; ++c_) {                                            \
            const int j_ = tid + (c_ << 8);                                         \
            const int r_ = j_ >> 3, cc_ = j_ & 7;                                   \
            const size_t go_ = cbase + (size_t)((tt_) * AKT + r_) * D_MODEL + cc_ * 8; \
            cp16(kb_ + r_ * 144 + cc_ * 16, kg + go_);                              \
            cp16(kb_ + KV_B + r_ * 144 + cc_ * 16, vg + go_);                       \
        }                                                                           \
    } while (0)

    // prologue: Q + stage0 (group0), stage1 (group1)
    #pragma unroll
    for (int c = 0; c < 4; ++c) {
        const int j = tid + (c << 8);
        const int r = j >> 3, cc = j & 7;
        cp16(qoff + r * 144 + cc * 16, qg + cbase + (size_t)(q0 + r) * D_MODEL + cc * 8);
    }
    AKV(0, 0);
    CP_COMMIT;
    AKV(1, 1);
    CP_COMMIT;

    float oacc[8][4];
    float mst[2] = { -1e30f, -1e30f }, lst[2] = { 0.f, 0.f };
    #pragma unroll
    for (int df = 0; df < 8; ++df)
        #pragma unroll
        for (int c = 0; c < 4; ++c) oacc[df][c] = 0.f;

    int s = 0, sf = 2;
    #pragma unroll 1
    for (int kt = 0; kt < NT; ++kt) {
        const uint32_t koff = sb + QS_B + s * 2 * KV_B;
        const uint32_t voff = koff + KV_B;

        CP_WAIT_GROUP(1);      // stage s ready (issued 2 iters ago)
        __syncthreads();       // all warps done with stage sf's old contents
        if (kt + 2 < NT) AKV(sf, kt + 2);
        CP_COMMIT;

        // ---- S = Q K^T (q pre-scaled by log2e/8) ----
        float sacc[8][4];
        #pragma unroll
        for (int nf = 0; nf < 8; ++nf)
            #pragma unroll
            for (int c = 0; c < 4; ++c) sacc[nf][c] = 0.f;

        #pragma unroll
        for (int s16 = 0; s16 < 4; ++s16) {
            const uint32_t kb = s16 * 32;
            uint32_t af[4];
            ldm4(af, qoff + (wrow + a_row) * 144 + a_cb + kb);
            #pragma unroll
            for (int nfp = 0; nfp < 4; ++nfp) {
                uint32_t t4[4];
                ldm4(t4, koff + (nfp * 16 + b_row) * 144 + b_cb + kb);
                mma_bf16(sacc[nfp * 2],     af, &t4[0]);
                mma_bf16(sacc[nfp * 2 + 1], af, &t4[2]);
            }
        }

        // ---- online softmax (log2 domain); P packed to registers ----
        uint32_t pr[2][8];
        #pragma unroll
        for (int h = 0; h < 2; ++h) {
            float rm = -1e30f;
            #pragma unroll
            for (int nf = 0; nf < 8; ++nf)
                rm = fmaxf(rm, fmaxf(sacc[nf][2 * h], sacc[nf][2 * h + 1]));
            rm = fmaxf(rm, __shfl_xor_sync(0xffffffffu, rm, 1));
            rm = fmaxf(rm, __shfl_xor_sync(0xffffffffu, rm, 2));
            const float mnew = fmaxf(mst[h], rm);
            const float corr = ex2(mst[h] - mnew);
            float ps = 0.f;
            #pragma unroll
            for (int nf = 0; nf < 8; ++nf) {
                const float p0 = ex2(sacc[nf][2 * h]     - mnew);
                const float p1 = ex2(sacc[nf][2 * h + 1] - mnew);
                ps += p0 + p1;
                __nv_bfloat162 hh = __floats2bfloat162_rn(p0, p1);
                pr[h][nf] = *(uint32_t*)&hh;
            }
            ps += __shfl_xor_sync(0xffffffffu, ps, 1);
            ps += __shfl_xor_sync(0xffffffffu, ps, 2);
            lst[h] = lst[h] * corr + ps;
            mst[h] = mnew;
            #pragma unroll
            for (int df = 0; df < 8; ++df) {
                oacc[df][2 * h]     *= corr;
                oacc[df][2 * h + 1] *= corr;
            }
        }

        // ---- O += P V  (P direct from registers: S C-frag == PV A-frag) ----
        #pragma unroll
        for (int s16 = 0; s16 < 4; ++s16) {
            uint32_t af[4];
            af[0] = pr[0][2 * s16];
            af[1] = pr[1][2 * s16];
            af[2] = pr[0][2 * s16 + 1];
            af[3] = pr[1][2 * s16 + 1];
            #pragma unroll
            for (int nfp = 0; nfp < 4; ++nfp) {
                uint32_t t4[4];
                ldm4t(t4, voff + (s16 * 16 + a_row) * 144 + a_cb + nfp * 32);
                mma_bf16(oacc[nfp * 2],     af, &t4[0]);
                mma_bf16(oacc[nfp * 2 + 1], af, &t4[2]);
            }
        }

        if (++s == 3) s = 0;
        if (++sf == 3) sf = 0;
    }
    #undef AKV

    // ---- finalize: /l, bf16 out (feeds o-proj GEMM) ----
    #pragma unroll
    for (int h = 0; h < 2; ++h) {
        const float inv = 1.f / lst[h];
        const int row = q0 + wrow + g + 8 * h;
        #pragma unroll
        for (int df = 0; df < 8; ++df) {
            __nv_bfloat162 o2 = __floats2bfloat162_rn(oacc[df][2 * h] * inv,
                                                      oacc[df][2 * h + 1] * inv);
            *(__nv_bfloat162*)(og + cbase + (size_t)row * D_MODEL + df * 8 + 2 * t) = o2;
        }
    }
}

// ---------------------------------- launch ------------------------------------------
extern "C" void kernel_launch(void* const* d_in, const int* in_sizes, int n_in,
                              void* d_out, int out_size) {
    const float* x    = (const float*)d_in[0];
    const float* ln_w = (const float*)d_in[1];
    const float* ln_b = (const float*)d_in[2];
    const float* Wq   = (const float*)d_in[3];
    const float* bq   = (const float*)d_in[4];
    const float* Wk   = (const float*)d_in[5];
    const float* bk   = (const float*)d_in[6];
    const float* Wv   = (const float*)d_in[7];
    const float* bv   = (const float*)d_in[8];
    const float* Wo   = (const float*)d_in[9];
    const float* bo   = (const float*)d_in[10];
    float* out = (float*)d_out;

    __nv_bfloat16 *xn, *q, *k, *v, *att, *wbuf;
    float2* rope;
    cudaGetSymbolAddress((void**)&xn,  g_xn);
    cudaGetSymbolAddress((void**)&q,   g_q);
    cudaGetSymbolAddress((void**)&k,   g_k);
    cudaGetSymbolAddress((void**)&v,   g_v);
    cudaGetSymbolAddress((void**)&att, g_att);
    cudaGetSymbolAddress((void**)&wbuf, g_w);
    cudaGetSymbolAddress((void**)&rope, g_rope);
    const size_t WN = (size_t)D_MODEL * D_MODEL;

    rope_table_kernel<<<SEQ * 32 / 256, 256>>>(rope);
    round_w_kernel<<<(int)(WN / 4 / 256), 256>>>(Wq, Wk, Wv, Wo, wbuf);
    ln_kernel<<<NTOK, 256>>>(x, ln_w, ln_b, xn);

    cudaFuncSetAttribute(gemm_qkv,   cudaFuncAttributeMaxDynamicSharedMemorySize, GEMM_SMEM);
    cudaFuncSetAttribute(gemm_oproj, cudaFuncAttributeMaxDynamicSharedMemorySize, GEMM_SMEM);

    gemm_qkv<<<dim3(24, NTOK / TBM), 256, GEMM_SMEM>>>(xn, wbuf, bq, bk, bv, q, k, v, rope);

    cudaFuncSetAttribute(attn_tc, cudaFuncAttributeMaxDynamicSharedMemorySize, ATT_SMEM);
    attn_tc<<<dim3(SEQ / AQ, NHEAD, BATCH), 256, ATT_SMEM>>>(q, k, v, att);

    gemm_oproj<<<dim3(D_MODEL / TBN, NTOK / TBM), 256, GEMM_SMEM>>>(att, wbuf + 3 * WN, bo, x, out);
}